// round 15
// baseline (speedup 1.0000x reference)
#include <cuda_runtime.h>
#include <cuda_fp16.h>

// ---------------------------------------------------------------------------
// H2GCN forward. Embed GEMM forked onto stream 2 (overlaps graph prep), fused
// MLP (hid in smem), tf32 tensor cores. SpMM: WARP per node (32 lanes x fp16x2),
// premultiplied fp16 shadow rows (dinv[v]*val), diag2 precomputed as g_wsq.
// ---------------------------------------------------------------------------

#define NN   100000
#define EE   800000
#define INF_ 512
#define HF   64
#define CF   40
#define ZF   320   // 5 * HF concat width

// ---- scratch (static device globals; no allocation anywhere) ----
__device__ float    g_deg[NN];
__device__ float    g_dinv[NN];
__device__ float    g_wsq[NN];           // du^2 * sum_v dv^2  (diag2)
__device__ int      g_rowptr[NN + 1];
__device__ int      g_cursor[NN];
__device__ int      g_part[512];
__device__ int      g_adj[2 * EE];
__device__ float    g_z[(size_t)NN * ZF];       // chunks: h,h1a,h2a,h1b,h2b (fp32)
__device__ float    g_curB[(size_t)NN * HF];    // cur = h1a + h2a (fp32)
__device__ unsigned g_h16[(size_t)4 * NN * 32]; // premult fp16x2 shadows: h,h1a,cur,h1b
__device__ float    g_sum[HF];
__device__ float    g_sumsq[HF];
__device__ int      g_is64;

// ---- fork/join stream + events (created before main; harness checkpoints later)
static cudaStream_t g_s2 = 0;
static cudaEvent_t  g_e1 = 0, g_e2 = 0;
static int g_fork = 0;
namespace {
struct SInit {
    SInit() {
        cudaStream_t s; cudaEvent_t a, b;
        if (cudaStreamCreateWithFlags(&s, cudaStreamNonBlocking) == cudaSuccess &&
            cudaEventCreateWithFlags(&a, cudaEventDisableTiming) == cudaSuccess &&
            cudaEventCreateWithFlags(&b, cudaEventDisableTiming) == cudaSuccess) {
            g_s2 = s; g_e1 = a; g_e2 = b; g_fork = 1;
        }
    }
};
SInit g_sinit;
}

// ---------------------------------------------------------------------------
__device__ __forceinline__ void load_edge(const int* __restrict__ ei32, int e,
                                          int& u, int& v) {
    if (g_is64) {
        u = ei32[2 * e];
        v = ei32[2 * EE + 2 * e];
    } else {
        u = ei32[e];
        v = ei32[EE + e];
    }
}

__global__ void k_zero() {
    int t = threadIdx.x;
    if (t < HF) g_sum[t] = 0.f;
    else if (t < 2 * HF) g_sumsq[t - HF] = 0.f;
}

// init + dtype probe (int64 LE values < 2^31 -> odd int32 words all zero)
__global__ void k_init(const int* __restrict__ ei32) {
    int i = blockIdx.x * blockDim.x + threadIdx.x;
    int stride = gridDim.x * blockDim.x;
    for (int j = i; j < NN; j += stride) {
        g_deg[j] = 0.f;
        g_cursor[j] = 0;
    }
    if (i == 0) {
        int oddzero = 1;
#pragma unroll
        for (int q = 1; q < 16; q += 2)
            if (ei32[q] != 0) oddzero = 0;
        g_is64 = oddzero;
    }
}

__global__ void k_deg(const int* __restrict__ ei32) {
    int e = blockIdx.x * blockDim.x + threadIdx.x;
    if (e >= EE) return;
    int u, v;
    load_edge(ei32, e, u, v);
    if ((unsigned)u >= NN || (unsigned)v >= NN || u == v) return;
    atomicAdd(g_deg + u, 1.f);
    atomicAdd(g_deg + v, 1.f);
}

// ---- 3-phase exclusive scan of (int)g_deg -> g_rowptr; also emits dinv ----
__global__ void k_scan1() {
    __shared__ int sh[256];
    int t = threadIdx.x;
    int i = blockIdx.x * 256 + t;
    float d = (i < NN) ? g_deg[i] : 0.f;
    if (i < NN) g_dinv[i] = (d > 0.f) ? rsqrtf(d) : 0.f;
    sh[t] = (int)d;
    __syncthreads();
    for (int off = 128; off > 0; off >>= 1) {
        if (t < off) sh[t] += sh[t + off];
        __syncthreads();
    }
    if (t == 0) g_part[blockIdx.x] = sh[0];
}

__global__ void k_scan2(int np) {  // 1 block, 512 threads
    __shared__ int sh[512];
    int t = threadIdx.x;
    int v = (t < np) ? g_part[t] : 0;
    sh[t] = v;
    __syncthreads();
    for (int off = 1; off < 512; off <<= 1) {
        int x = (t >= off) ? sh[t - off] : 0;
        __syncthreads();
        sh[t] += x;
        __syncthreads();
    }
    if (t < np) g_part[t] = sh[t] - v;  // exclusive
    if (t == 511) g_rowptr[NN] = sh[511];
}

__global__ void k_scan3() {
    __shared__ int sh[256];
    int t = threadIdx.x;
    int i = blockIdx.x * 256 + t;
    int v = (i < NN) ? (int)g_deg[i] : 0;
    sh[t] = v;
    __syncthreads();
    for (int off = 1; off < 256; off <<= 1) {
        int x = (t >= off) ? sh[t - off] : 0;
        __syncthreads();
        sh[t] += x;
        __syncthreads();
    }
    if (i < NN) g_rowptr[i] = g_part[blockIdx.x] + sh[t] - v;
}

__global__ void k_fill(const int* __restrict__ ei32) {
    int e = blockIdx.x * blockDim.x + threadIdx.x;
    if (e >= EE) return;
    int u, v;
    load_edge(ei32, e, u, v);
    if ((unsigned)u >= NN || (unsigned)v >= NN || u == v) return;
    int p = atomicAdd(g_cursor + u, 1);
    g_adj[g_rowptr[u] + p] = v;
    int q = atomicAdd(g_cursor + v, 1);
    g_adj[g_rowptr[v] + q] = u;
}

// wsq[u] = dinv[u]^2 * sum_{v in adj(u)} dinv[v]^2   (== diag2, hop-invariant)
__global__ void k_wsq() {
    int node = blockIdx.x * 8 + (threadIdx.x >> 5);
    if (node >= NN) return;
    int lane = threadIdx.x & 31;
    int s = g_rowptr[node], e = g_rowptr[node + 1];
    float acc = 0.f;
    for (int j = s + lane; j < e; j += 32) {
        float dv = g_dinv[g_adj[j]];
        acc += dv * dv;
    }
#pragma unroll
    for (int m = 16; m; m >>= 1) acc += __shfl_xor_sync(0xffffffffu, acc, m);
    if (lane == 0) {
        float du = g_dinv[node];
        g_wsq[node] = du * du * acc;
    }
}

// ---------------------------------------------------------------------------
// tf32 helpers / GEMM constants
// ---------------------------------------------------------------------------
__device__ __forceinline__ unsigned f2tf(float f) {
    unsigned r;
    asm("cvt.rna.tf32.f32 %0, %1;" : "=r"(r) : "f"(f));
    return r;
}
__device__ __forceinline__ unsigned u2tf(unsigned u) {
    return f2tf(__uint_as_float(u));
}

#define SAS 20       // pipeline row stride (words)
#define STG 3        // pipeline stages
#define A_STG (128 * SAS)
#define B_STG (64 * SAS)
#define HS  68       // stage-2 hid/W2 row stride (words)

__device__ __forceinline__ void ldsm4(unsigned& r0, unsigned& r1,
                                      unsigned& r2, unsigned& r3, unsigned addr) {
    asm volatile("ldmatrix.sync.aligned.m8n8.x4.shared.b16 {%0,%1,%2,%3}, [%4];"
                 : "=r"(r0), "=r"(r1), "=r"(r2), "=r"(r3) : "r"(addr));
}

#define MMA_TF32(acc, a, b)                                                    \
    asm volatile(                                                              \
        "mma.sync.aligned.m16n8k8.row.col.f32.tf32.tf32.f32 "                  \
        "{%0,%1,%2,%3}, {%4,%5,%6,%7}, {%8,%9}, {%0,%1,%2,%3};"                \
        : "+f"((acc)[0]), "+f"((acc)[1]), "+f"((acc)[2]), "+f"((acc)[3])       \
        : "r"((a)[0]), "r"((a)[1]), "r"((a)[2]), "r"((a)[3]),                  \
          "r"((b)[0]), "r"((b)[1]))

#define PIPE_ISSUE(st, k0)                                                     \
    {                                                                          \
        unsigned dA = dstA0 + (st) * (A_STG * 4);                              \
        const float* sA = srcAbase + (k0);                                     \
        asm volatile("cp.async.cg.shared.global [%0], [%1], 16, %2;"           \
                     :: "r"(dA), "l"(sA), "r"(pa));                            \
        asm volatile("cp.async.cg.shared.global [%0], [%1], 16, %2;"           \
                     :: "r"(dA + 32), "l"(sA + 8), "r"(pa));                   \
        unsigned dB = dstB0 + (st) * (B_STG * 4);                              \
        const float* sB = srcBbase + (k0);                                     \
        asm volatile("cp.async.cg.shared.global [%0], [%1], 16, %2;"           \
                     :: "r"(dB), "l"(sB), "r"(pb));                            \
    }

#define PIPE_MAINLOOP(KVAL)                                                    \
    int iters = (KVAL) >> 4;                                                   \
    PIPE_ISSUE(0, 0);                                                          \
    asm volatile("cp.async.commit_group;");                                    \
    PIPE_ISSUE(1, 16);                                                         \
    asm volatile("cp.async.commit_group;");                                    \
    int stage = 0;                                                             \
    for (int i = 0; i < iters; i++) {                                          \
        asm volatile("cp.async.wait_group 1;");                                \
        __syncthreads();                                                       \
        int nx = i + 2;                                                        \
        if (nx < iters) { int nst = nx % STG; PIPE_ISSUE(nst, nx * 16); }      \
        asm volatile("cp.async.commit_group;");                                \
        unsigned aB = sa_A + (unsigned)(stage * (A_STG * 4) + aoffw * 4);      \
        unsigned bB = sa_B + (unsigned)(stage * (B_STG * 4) + boffw * 4);      \
        _Pragma("unroll")                                                      \
        for (int ks = 0; ks < 2; ks++) {                                       \
            unsigned kbb = ks * 32;                                            \
            unsigned a[2][4];                                                  \
            ldsm4(a[0][0], a[0][1], a[0][2], a[0][3], aB + kbb);               \
            ldsm4(a[1][0], a[1][1], a[1][2], a[1][3], aB + kbb + 16 * SAS * 4);\
            unsigned b[4][2];                                                  \
            ldsm4(b[0][0], b[0][1], b[1][0], b[1][1], bB + kbb);               \
            ldsm4(b[2][0], b[2][1], b[3][0], b[3][1], bB + kbb + 16 * SAS * 4);\
            _Pragma("unroll")                                                  \
            for (int im = 0; im < 2; im++)                                     \
                _Pragma("unroll")                                              \
                for (int q = 0; q < 4; q++) a[im][q] = u2tf(a[im][q]);         \
            _Pragma("unroll")                                                  \
            for (int in = 0; in < 4; in++) {                                   \
                b[in][0] = u2tf(b[in][0]);                                     \
                b[in][1] = u2tf(b[in][1]);                                     \
            }                                                                  \
            _Pragma("unroll")                                                  \
            for (int im = 0; im < 2; im++)                                     \
                _Pragma("unroll")                                              \
                for (int in = 0; in < 4; in++) MMA_TF32(acc[im][in], a[im], b[in]); \
        }                                                                      \
        stage = (stage + 1 == STG) ? 0 : stage + 1;                            \
    }

// ---------------------------------------------------------------------------
// Embed GEMM: g_z chunk0 = relu(x @ W_embed^T + b), fused BN column stats.
// ---------------------------------------------------------------------------
__global__ void k_mma(const float* __restrict__ Ain, int M, int K, int lda,
                      const float* __restrict__ B, int Nc, int ldb,
                      const float* __restrict__ bias) {
    float* C = g_z;
    const int ldc = ZF;
    const float* A = Ain;

    __shared__ unsigned As[STG * A_STG];
    __shared__ unsigned Bs[STG * B_STG];

    int t = threadIdx.x;
    int w = t >> 5, lane = t & 31;
    int g = lane >> 2, tig = lane & 3;
    int wm = (w & 3) * 32;
    int wn = (w >> 2) * 32;
    int row0 = blockIdx.x * 128;

    float acc[2][4][4];
#pragma unroll
    for (int im = 0; im < 2; im++)
#pragma unroll
        for (int in = 0; in < 4; in++)
#pragma unroll
            for (int q = 0; q < 4; q++) acc[im][in][q] = 0.f;

    int ar = t >> 1, ac = t & 1;
    int br = t >> 2, bc4 = t & 3;
    int gr = row0 + ar;
    int pa = (gr < M) ? 16 : 0;
    int pb = (br < Nc) ? 16 : 0;
    const float* srcAbase = A + (size_t)(gr < M ? gr : M - 1) * lda + ac * 4;
    const float* srcBbase = B + (size_t)(br < Nc ? br : 0) * ldb + bc4 * 4;

    unsigned sa_A = (unsigned)__cvta_generic_to_shared(&As[0]);
    unsigned sa_B = (unsigned)__cvta_generic_to_shared(&Bs[0]);
    unsigned dstA0 = sa_A + (unsigned)(ar * SAS + ac * 4) * 4;
    unsigned dstB0 = sa_B + (unsigned)(br * SAS + bc4 * 4) * 4;

    int lrow = lane & 7, lt = lane >> 3;
    int aoffw = (wm + (lt & 1) * 8 + lrow) * SAS + (lt >> 1) * 4;
    int boffw = (wn + (lt >> 1) * 8 + lrow) * SAS + (lt & 1) * 4;

    PIPE_MAINLOOP(K)

    // epilogue + fused BN statistics
    float scol[8], qcol[8];
#pragma unroll
    for (int k2 = 0; k2 < 8; k2++) { scol[k2] = 0.f; qcol[k2] = 0.f; }

#pragma unroll
    for (int im = 0; im < 2; im++) {
#pragma unroll
        for (int in = 0; in < 4; in++) {
            int Cc = wn + in * 8 + 2 * tig;
            float bx = bias[Cc], by = bias[Cc + 1];
            int R0 = row0 + wm + im * 16 + g;
            float v0 = fmaxf(acc[im][in][0] + bx, 0.f);
            float v1 = fmaxf(acc[im][in][1] + by, 0.f);
            float v2 = fmaxf(acc[im][in][2] + bx, 0.f);
            float v3 = fmaxf(acc[im][in][3] + by, 0.f);
            if (R0 < M)
                *reinterpret_cast<float2*>(C + (size_t)R0 * ldc + Cc) = make_float2(v0, v1);
            if (R0 + 8 < M)
                *reinterpret_cast<float2*>(C + (size_t)(R0 + 8) * ldc + Cc) = make_float2(v2, v3);
            float m0 = (R0 < M) ? 1.f : 0.f;
            float m1 = (R0 + 8 < M) ? 1.f : 0.f;
            scol[in * 2 + 0] += m0 * v0 + m1 * v2;
            scol[in * 2 + 1] += m0 * v1 + m1 * v3;
            qcol[in * 2 + 0] += m0 * v0 * v0 + m1 * v2 * v2;
            qcol[in * 2 + 1] += m0 * v1 * v1 + m1 * v3 * v3;
        }
    }
#pragma unroll
    for (int k2 = 0; k2 < 8; k2++) {
#pragma unroll
        for (int mask = 4; mask < 32; mask <<= 1) {
            scol[k2] += __shfl_xor_sync(0xffffffffu, scol[k2], mask);
            qcol[k2] += __shfl_xor_sync(0xffffffffu, qcol[k2], mask);
        }
    }
    if (g == 0) {
#pragma unroll
        for (int k2 = 0; k2 < 8; k2++) {
            int col = wn + (k2 >> 1) * 8 + 2 * tig + (k2 & 1);
            atomicAdd(&g_sum[col], scol[k2]);
            atomicAdd(&g_sumsq[col], qcol[k2]);
        }
    }
}

// ---------------------------------------------------------------------------
// Fused MLP: out = relu(z @ W1^T + b1) @ W2^T + b2, hid tile kept in smem.
// ---------------------------------------------------------------------------
__global__ void k_mlp(const float* __restrict__ W1, const float* __restrict__ b1,
                      const float* __restrict__ W2, const float* __restrict__ b2,
                      float* __restrict__ out) {
    extern __shared__ unsigned dsm[];
    unsigned* As  = dsm;
    unsigned* Bs  = dsm + STG * A_STG;
    unsigned* hid = dsm;               // reused after sync
    unsigned* W2s = dsm + 128 * HS;

    const float* A = g_z;
    const int M = NN, K = ZF, lda = ZF, Nc = HF, ldb = ZF;

    int t = threadIdx.x;
    int w = t >> 5, lane = t & 31;
    int g = lane >> 2, tig = lane & 3;
    int wm = (w & 3) * 32;
    int wn = (w >> 2) * 32;
    int row0 = blockIdx.x * 128;

    float acc[2][4][4];
#pragma unroll
    for (int im = 0; im < 2; im++)
#pragma unroll
        for (int in = 0; in < 4; in++)
#pragma unroll
            for (int q = 0; q < 4; q++) acc[im][in][q] = 0.f;

    int ar = t >> 1, ac = t & 1;
    int br = t >> 2, bc4 = t & 3;
    int gr = row0 + ar;
    int pa = (gr < M) ? 16 : 0;
    int pb = (br < Nc) ? 16 : 0;
    const float* srcAbase = A + (size_t)(gr < M ? gr : M - 1) * lda + ac * 4;
    const float* srcBbase = W1 + (size_t)(br < Nc ? br : 0) * ldb + bc4 * 4;

    unsigned sa_A = (unsigned)__cvta_generic_to_shared(&As[0]);
    unsigned sa_B = (unsigned)__cvta_generic_to_shared(&Bs[0]);
    unsigned dstA0 = sa_A + (unsigned)(ar * SAS + ac * 4) * 4;
    unsigned dstB0 = sa_B + (unsigned)(br * SAS + bc4 * 4) * 4;

    int lrow = lane & 7, lt = lane >> 3;
    int aoffw = (wm + (lt & 1) * 8 + lrow) * SAS + (lt >> 1) * 4;
    int boffw = (wn + (lt >> 1) * 8 + lrow) * SAS + (lt & 1) * 4;

    PIPE_MAINLOOP(K)

    __syncthreads();  // all warps done with As/Bs; reuse as hid

    // stage-1 epilogue -> smem hid (tf32 bits)
#pragma unroll
    for (int im = 0; im < 2; im++) {
#pragma unroll
        for (int in = 0; in < 4; in++) {
            int Cc = wn + in * 8 + 2 * tig;
            float bx = b1[Cc], by = b1[Cc + 1];
            int rl = wm + im * 16 + g;
            hid[rl * HS + Cc]           = f2tf(fmaxf(acc[im][in][0] + bx, 0.f));
            hid[rl * HS + Cc + 1]       = f2tf(fmaxf(acc[im][in][1] + by, 0.f));
            hid[(rl + 8) * HS + Cc]     = f2tf(fmaxf(acc[im][in][2] + bx, 0.f));
            hid[(rl + 8) * HS + Cc + 1] = f2tf(fmaxf(acc[im][in][3] + by, 0.f));
        }
    }
    // load W2 (40x64) into smem, zero-pad rows 40..63
    for (int id = t; id < 64 * 64; id += 256) {
        int r = id >> 6, c = id & 63;
        W2s[r * HS + c] = (r < CF) ? f2tf(W2[r * 64 + c]) : 0u;
    }
    __syncthreads();

    // stage 2: out_tile = hid(128x64) @ W2^T (64x40)
    float acc2[2][4][4];
#pragma unroll
    for (int im = 0; im < 2; im++)
#pragma unroll
        for (int in = 0; in < 4; in++)
#pragma unroll
            for (int q = 0; q < 4; q++) acc2[im][in][q] = 0.f;

    unsigned sa_h  = (unsigned)__cvta_generic_to_shared(hid);
    unsigned sa_w2 = (unsigned)__cvta_generic_to_shared(W2s);
    unsigned a2off = sa_h  + (unsigned)((wm + (lt & 1) * 8 + lrow) * HS + (lt >> 1) * 4) * 4;
    unsigned b2off = sa_w2 + (unsigned)((wn + (lt >> 1) * 8 + lrow) * HS + (lt & 1) * 4) * 4;

#pragma unroll
    for (int ks = 0; ks < 8; ks++) {
        unsigned kbb = ks * 32;
        unsigned a[2][4], b[4][2];
        ldsm4(a[0][0], a[0][1], a[0][2], a[0][3], a2off + kbb);
        ldsm4(a[1][0], a[1][1], a[1][2], a[1][3], a2off + kbb + 16 * HS * 4);
        ldsm4(b[0][0], b[0][1], b[1][0], b[1][1], b2off + kbb);
        ldsm4(b[2][0], b[2][1], b[3][0], b[3][1], b2off + kbb + 16 * HS * 4);
#pragma unroll
        for (int im = 0; im < 2; im++)
#pragma unroll
            for (int in = 0; in < 4; in++) MMA_TF32(acc2[im][in], a[im], b[in]);
    }

    // stage-2 epilogue -> out [NN x CF]
#pragma unroll
    for (int im = 0; im < 2; im++) {
#pragma unroll
        for (int in = 0; in < 4; in++) {
            int Cc = wn + in * 8 + 2 * tig;
            if (Cc >= CF) continue;
            float bx = b2[Cc], by = b2[Cc + 1];
            int R0 = row0 + wm + im * 16 + g;
            if (R0 < M)
                *reinterpret_cast<float2*>(out + (size_t)R0 * CF + Cc) =
                    make_float2(acc2[im][in][0] + bx, acc2[im][in][1] + by);
            if (R0 + 8 < M)
                *reinterpret_cast<float2*>(out + (size_t)(R0 + 8) * CF + Cc) =
                    make_float2(acc2[im][in][2] + bx, acc2[im][in][3] + by);
        }
    }
}

// ---------------------------------------------------------------------------
// BN finalize + apply; writes premultiplied fp16 shadow (dinv[u] * h_bn).
// ---------------------------------------------------------------------------
__global__ void k_bnapply(const float* __restrict__ gamma, const float* __restrict__ beta) {
    int i = blockIdx.x * blockDim.x + threadIdx.x;
    if (i >= NN * 32) return;
    int node = i >> 5, fp = (i & 31) * 2;
    float2 sc, sh;
#pragma unroll
    for (int q = 0; q < 2; q++) {
        int f = fp + q;
        float mu = g_sum[f] * (1.f / (float)NN);
        float var = g_sumsq[f] * (1.f / (float)NN) - mu * mu;
        float s = gamma[f] * rsqrtf(var + 1e-5f);
        float b = beta[f] - mu * s;
        if (q == 0) { sc.x = s; sh.x = b; } else { sc.y = s; sh.y = b; }
    }
    size_t idx = (size_t)node * ZF + fp;
    float2 v = *reinterpret_cast<float2*>(g_z + idx);
    v.x = v.x * sc.x + sh.x;
    v.y = v.y * sc.y + sh.y;
    *reinterpret_cast<float2*>(g_z + idx) = v;
    float dn = g_dinv[node];
    __half2 hv = __floats2half2_rn(v.x * dn, v.y * dn);
    g_h16[(size_t)node * 32 + (i & 31)] = *reinterpret_cast<unsigned*>(&hv);
}

// ---------------------------------------------------------------------------
// SpMM: dst[u] = du * sum_{v in adj(u)} shadow[srcC][v]   (rows premultiplied)
//        (- wsq[u] * prev[u]  if prevMode)
// WARP per node: 32 lanes x fp16x2 (4 B/lane) -> one 128 B line per edge,
// no intra-warp divergence, 4 indep outstanding loads per lane (unroll 4).
// dstC >= 0: write premultiplied shadow of dst. writeCur: curB = z[srcZOff]+dst
// (fp32) plus premultiplied shadow chunk 2.
// ---------------------------------------------------------------------------
__global__ void k_spmm(int srcC, int prevMode, int dstOff, int dstC,
                       int writeCur, int srcZOff) {
    int node = blockIdx.x * 8 + (threadIdx.x >> 5);
    if (node >= NN) return;
    int lane = threadIdx.x & 31;

    const unsigned* src16 = g_h16 + (size_t)srcC * NN * 32;

    int s = g_rowptr[node];
    int e = g_rowptr[node + 1];
    float ax = 0.f, ay = 0.f;
#pragma unroll 4
    for (int j = s; j < e; j++) {
        int v = g_adj[j];
        unsigned rv = __ldg(src16 + (size_t)v * 32 + lane);
        float2 p = __half22float2(*reinterpret_cast<__half2*>(&rv));
        ax += p.x;
        ay += p.y;
    }
    float du = g_dinv[node];
    ax *= du;
    ay *= du;
    if (prevMode) {
        const float* prev = (prevMode == 1) ? g_z : g_curB;
        int pld = (prevMode == 1) ? ZF : HF;
        float wsq = g_wsq[node];
        float2 p = *reinterpret_cast<const float2*>(prev + (size_t)node * pld + lane * 2);
        ax -= wsq * p.x;
        ay -= wsq * p.y;
    }
    *reinterpret_cast<float2*>(g_z + dstOff + (size_t)node * ZF + lane * 2) =
        make_float2(ax, ay);
    if (dstC >= 0) {
        __half2 hv = __floats2half2_rn(ax * du, ay * du);
        g_h16[(size_t)dstC * NN * 32 + (size_t)node * 32 + lane] =
            *reinterpret_cast<unsigned*>(&hv);
    }
    if (writeCur) {
        float2 sown = *reinterpret_cast<const float2*>(
            g_z + srcZOff + (size_t)node * ZF + lane * 2);
        float cx = sown.x + ax, cy = sown.y + ay;
        *reinterpret_cast<float2*>(g_curB + (size_t)node * HF + lane * 2) =
            make_float2(cx, cy);
        __half2 hv = __floats2half2_rn(cx * du, cy * du);
        g_h16[(size_t)2 * NN * 32 + (size_t)node * 32 + lane] =
            *reinterpret_cast<unsigned*>(&hv);
    }
}

// ---------------------------------------------------------------------------
extern "C" void kernel_launch(void* const* d_in, const int* in_sizes, int n_in,
                              void* d_out, int out_size) {
    const float* x       = (const float*)d_in[0];
    const int*   ei32    = (const int*)d_in[1];
    const float* W_embed = (const float*)d_in[2];
    const float* b_embed = (const float*)d_in[3];
    const float* bn_g    = (const float*)d_in[4];
    const float* bn_b    = (const float*)d_in[5];
    const float* W1      = (const float*)d_in[6];
    const float* b1      = (const float*)d_in[7];
    const float* W2      = (const float*)d_in[8];
    const float* b2      = (const float*)d_in[9];
    float* out = (float*)d_out;

    const int NPART = (NN + 255) / 256;  // 391
    int mma_grid = (NN + 127) / 128;
    int warp8_grid = (NN + 7) / 8;

    // zero BN accumulators, then fork embed GEMM onto s2 (overlaps graph prep)
    k_zero<<<1, 128>>>();
    if (g_fork) {
        cudaEventRecord(g_e1, 0);
        cudaStreamWaitEvent(g_s2, g_e1, 0);
        k_mma<<<mma_grid, 256, 0, g_s2>>>(x, NN, INF_, INF_, W_embed, HF, INF_, b_embed);
        cudaEventRecord(g_e2, g_s2);
    } else {
        k_mma<<<mma_grid, 256>>>(x, NN, INF_, INF_, W_embed, HF, INF_, b_embed);
    }

    // graph prep on main stream (independent of embed)
    k_init<<<256, 256>>>(ei32);
    k_deg<<<(EE + 255) / 256, 256>>>(ei32);
    k_scan1<<<NPART, 256>>>();
    k_scan2<<<1, 512>>>(NPART);
    k_scan3<<<NPART, 256>>>();
    k_fill<<<(EE + 255) / 256, 256>>>(ei32);
    k_wsq<<<warp8_grid, 256>>>();

    // join: BN apply needs embed output + stats (+ dinv for the shadow)
    if (g_fork) cudaStreamWaitEvent(0, g_e2, 0);
    k_bnapply<<<(NN * 32 + 255) / 256, 256>>>(bn_g, bn_b);

    // hop 1: h1a = A h ; h2a = A h1a - diag2*h ; curB = h1a + h2a
    k_spmm<<<warp8_grid, 256>>>(0, 0, 1 * HF, 1, 0, 0);
    k_spmm<<<warp8_grid, 256>>>(1, 1, 2 * HF, -1, 1, 1 * HF);
    // hop 2: h1b = A curB ; h2b = A h1b - diag2*curB
    k_spmm<<<warp8_grid, 256>>>(2, 0, 3 * HF, 3, 0, 0);
    k_spmm<<<warp8_grid, 256>>>(3, 2, 4 * HF, -1, 0, 0);

    // fused MLP
    cudaFuncSetAttribute(k_mlp, cudaFuncAttributeMaxDynamicSharedMemorySize, 52224);
    k_mlp<<<mma_grid, 256, 52224>>>(W1, b1, W2, b2, out);
}

// round 17
// speedup vs baseline: 1.2777x; 1.2777x over previous
#include <cuda_runtime.h>
#include <cuda_fp16.h>

// ---------------------------------------------------------------------------
// H2GCN forward. Embed GEMM (tf32, fused BN stats) forked onto stream 2.
// z stored fp16 (g_z16); SpMM: half-warp per node over premultiplied fp16
// shadows; fused MLP on fp16 mma.m16n8k16 (fp32 accum), W1/W2 pre-converted.
// R17 fix: guard B-tile cp.async in k_mlp (threads >=128 were zero-filling
// the same smem addresses -> race).
// ---------------------------------------------------------------------------

#define NN   100000
#define EE   800000
#define INF_ 512
#define HF   64
#define CF   40
#define ZF   320   // 5 * HF concat width
#define ZW   160   // ZF/2 words per node in g_z16

// ---- scratch (static device globals; no allocation anywhere) ----
__device__ float    g_deg[NN];
__device__ float    g_dinv[NN];
__device__ float    g_wsq[NN];            // du^2 * sum_v dv^2  (diag2)
__device__ int      g_rowptr[NN + 1];
__device__ int      g_cursor[NN];
__device__ int      g_part[512];
__device__ int      g_adj[2 * EE];
__device__ float    g_z[(size_t)NN * HF];        // pre-BN h (fp32)
__device__ unsigned g_z16[(size_t)NN * ZW];      // fp16x2 z rows: h,h1a,h2a,h1b,h2b
__device__ unsigned g_cur16[(size_t)NN * 32];    // raw fp16 cur
__device__ unsigned g_h16[(size_t)4 * NN * 32];  // premult shadows: h,h1a,cur,h1b
__device__ unsigned g_W116[64 * 160];            // W1 fp16 (64 x 320)
__device__ unsigned g_W216[64 * 32];             // W2 fp16 (64 x 64, zero-padded)
__device__ float    g_sum[HF];
__device__ float    g_sumsq[HF];
__device__ int      g_is64;

// ---- fork/join stream + events
static cudaStream_t g_s2 = 0;
static cudaEvent_t  g_e1 = 0, g_e2 = 0;
static int g_fork = 0;
namespace {
struct SInit {
    SInit() {
        cudaStream_t s; cudaEvent_t a, b;
        if (cudaStreamCreateWithFlags(&s, cudaStreamNonBlocking) == cudaSuccess &&
            cudaEventCreateWithFlags(&a, cudaEventDisableTiming) == cudaSuccess &&
            cudaEventCreateWithFlags(&b, cudaEventDisableTiming) == cudaSuccess) {
            g_s2 = s; g_e1 = a; g_e2 = b; g_fork = 1;
        }
    }
};
SInit g_sinit;
}

// ---------------------------------------------------------------------------
__device__ __forceinline__ void load_edge(const int* __restrict__ ei32, int e,
                                          int& u, int& v) {
    if (g_is64) {
        u = ei32[2 * e];
        v = ei32[2 * EE + 2 * e];
    } else {
        u = ei32[e];
        v = ei32[EE + e];
    }
}

__global__ void k_zero() {
    int t = threadIdx.x;
    if (t < HF) g_sum[t] = 0.f;
    else if (t < 2 * HF) g_sumsq[t - HF] = 0.f;
}

__global__ void k_init(const int* __restrict__ ei32) {
    int i = blockIdx.x * blockDim.x + threadIdx.x;
    int stride = gridDim.x * blockDim.x;
    for (int j = i; j < NN; j += stride) {
        g_deg[j] = 0.f;
        g_cursor[j] = 0;
    }
    if (i == 0) {
        int oddzero = 1;
#pragma unroll
        for (int q = 1; q < 16; q += 2)
            if (ei32[q] != 0) oddzero = 0;
        g_is64 = oddzero;
    }
}

__global__ void k_deg(const int* __restrict__ ei32) {
    int e = blockIdx.x * blockDim.x + threadIdx.x;
    if (e >= EE) return;
    int u, v;
    load_edge(ei32, e, u, v);
    if ((unsigned)u >= NN || (unsigned)v >= NN || u == v) return;
    atomicAdd(g_deg + u, 1.f);
    atomicAdd(g_deg + v, 1.f);
}

__global__ void k_scan1() {
    __shared__ int sh[256];
    int t = threadIdx.x;
    int i = blockIdx.x * 256 + t;
    float d = (i < NN) ? g_deg[i] : 0.f;
    if (i < NN) g_dinv[i] = (d > 0.f) ? rsqrtf(d) : 0.f;
    sh[t] = (int)d;
    __syncthreads();
    for (int off = 128; off > 0; off >>= 1) {
        if (t < off) sh[t] += sh[t + off];
        __syncthreads();
    }
    if (t == 0) g_part[blockIdx.x] = sh[0];
}

__global__ void k_scan2(int np) {
    __shared__ int sh[512];
    int t = threadIdx.x;
    int v = (t < np) ? g_part[t] : 0;
    sh[t] = v;
    __syncthreads();
    for (int off = 1; off < 512; off <<= 1) {
        int x = (t >= off) ? sh[t - off] : 0;
        __syncthreads();
        sh[t] += x;
        __syncthreads();
    }
    if (t < np) g_part[t] = sh[t] - v;
    if (t == 511) g_rowptr[NN] = sh[511];
}

__global__ void k_scan3() {
    __shared__ int sh[256];
    int t = threadIdx.x;
    int i = blockIdx.x * 256 + t;
    int v = (i < NN) ? (int)g_deg[i] : 0;
    sh[t] = v;
    __syncthreads();
    for (int off = 1; off < 256; off <<= 1) {
        int x = (t >= off) ? sh[t - off] : 0;
        __syncthreads();
        sh[t] += x;
        __syncthreads();
    }
    if (i < NN) g_rowptr[i] = g_part[blockIdx.x] + sh[t] - v;
}

__global__ void k_fill(const int* __restrict__ ei32) {
    int e = blockIdx.x * blockDim.x + threadIdx.x;
    if (e >= EE) return;
    int u, v;
    load_edge(ei32, e, u, v);
    if ((unsigned)u >= NN || (unsigned)v >= NN || u == v) return;
    int p = atomicAdd(g_cursor + u, 1);
    g_adj[g_rowptr[u] + p] = v;
    int q = atomicAdd(g_cursor + v, 1);
    g_adj[g_rowptr[v] + q] = u;
}

__global__ void k_wsq() {
    int node = blockIdx.x * 8 + (threadIdx.x >> 5);
    if (node >= NN) return;
    int lane = threadIdx.x & 31;
    int s = g_rowptr[node], e = g_rowptr[node + 1];
    float acc = 0.f;
    for (int j = s + lane; j < e; j += 32) {
        float dv = g_dinv[g_adj[j]];
        acc += dv * dv;
    }
#pragma unroll
    for (int m = 16; m; m >>= 1) acc += __shfl_xor_sync(0xffffffffu, acc, m);
    if (lane == 0) {
        float du = g_dinv[node];
        g_wsq[node] = du * du * acc;
    }
}

// convert W1 -> fp16 (64x320) and W2 -> fp16 (64x64, zero-pad rows >= CF)
__global__ void k_cvtW(const float* __restrict__ W1, const float* __restrict__ W2) {
    int i = blockIdx.x * blockDim.x + threadIdx.x;
    if (i < 64 * 160) {
        __half2 h = __floats2half2_rn(W1[2 * i], W1[2 * i + 1]);
        g_W116[i] = *reinterpret_cast<unsigned*>(&h);
    }
    if (i < 64 * 32) {
        int r = i >> 5, c2 = i & 31;
        float a = 0.f, b = 0.f;
        if (r < CF) { a = W2[r * 64 + 2 * c2]; b = W2[r * 64 + 2 * c2 + 1]; }
        __half2 h = __floats2half2_rn(a, b);
        g_W216[i] = *reinterpret_cast<unsigned*>(&h);
    }
}

// ---------------------------------------------------------------------------
// tf32 helpers / embed GEMM (unchanged math)
// ---------------------------------------------------------------------------
__device__ __forceinline__ unsigned f2tf(float f) {
    unsigned r;
    asm("cvt.rna.tf32.f32 %0, %1;" : "=r"(r) : "f"(f));
    return r;
}
__device__ __forceinline__ unsigned u2tf(unsigned u) {
    return f2tf(__uint_as_float(u));
}

#define SAS 20
#define STG 3
#define A_STG (128 * SAS)
#define B_STG (64 * SAS)

__device__ __forceinline__ void ldsm4(unsigned& r0, unsigned& r1,
                                      unsigned& r2, unsigned& r3, unsigned addr) {
    asm volatile("ldmatrix.sync.aligned.m8n8.x4.shared.b16 {%0,%1,%2,%3}, [%4];"
                 : "=r"(r0), "=r"(r1), "=r"(r2), "=r"(r3) : "r"(addr));
}

#define MMA_TF32(acc, a, b)                                                    \
    asm volatile(                                                              \
        "mma.sync.aligned.m16n8k8.row.col.f32.tf32.tf32.f32 "                  \
        "{%0,%1,%2,%3}, {%4,%5,%6,%7}, {%8,%9}, {%0,%1,%2,%3};"                \
        : "+f"((acc)[0]), "+f"((acc)[1]), "+f"((acc)[2]), "+f"((acc)[3])       \
        : "r"((a)[0]), "r"((a)[1]), "r"((a)[2]), "r"((a)[3]),                  \
          "r"((b)[0]), "r"((b)[1]))

#define MMA_F16(acc, a, b)                                                     \
    asm volatile(                                                              \
        "mma.sync.aligned.m16n8k16.row.col.f32.f16.f16.f32 "                   \
        "{%0,%1,%2,%3}, {%4,%5,%6,%7}, {%8,%9}, {%0,%1,%2,%3};"                \
        : "+f"((acc)[0]), "+f"((acc)[1]), "+f"((acc)[2]), "+f"((acc)[3])       \
        : "r"((a)[0]), "r"((a)[1]), "r"((a)[2]), "r"((a)[3]),                  \
          "r"((b)[0]), "r"((b)[1]))

__global__ void k_mma(const float* __restrict__ Ain, int M, int K, int lda,
                      const float* __restrict__ B, int Nc, int ldb,
                      const float* __restrict__ bias) {
    float* C = g_z;
    const int ldc = HF;
    const float* A = Ain;

    __shared__ unsigned As[STG * A_STG];
    __shared__ unsigned Bs[STG * B_STG];

    int t = threadIdx.x;
    int w = t >> 5, lane = t & 31;
    int g = lane >> 2, tig = lane & 3;
    int wm = (w & 3) * 32;
    int wn = (w >> 2) * 32;
    int row0 = blockIdx.x * 128;

    float acc[2][4][4];
#pragma unroll
    for (int im = 0; im < 2; im++)
#pragma unroll
        for (int in = 0; in < 4; in++)
#pragma unroll
            for (int q = 0; q < 4; q++) acc[im][in][q] = 0.f;

    int ar = t >> 1, ac = t & 1;
    int br = t >> 2, bc4 = t & 3;
    int gr = row0 + ar;
    int pa = (gr < M) ? 16 : 0;
    int pb = (br < Nc) ? 16 : 0;
    const float* srcAbase = A + (size_t)(gr < M ? gr : M - 1) * lda + ac * 4;
    const float* srcBbase = B + (size_t)(br < Nc ? br : 0) * ldb + bc4 * 4;

    unsigned sa_A = (unsigned)__cvta_generic_to_shared(&As[0]);
    unsigned sa_B = (unsigned)__cvta_generic_to_shared(&Bs[0]);
    unsigned dstA0 = sa_A + (unsigned)(ar * SAS + ac * 4) * 4;
    unsigned dstB0 = sa_B + (unsigned)(br * SAS + bc4 * 4) * 4;

    int lrow = lane & 7, lt = lane >> 3;
    int aoffw = (wm + (lt & 1) * 8 + lrow) * SAS + (lt >> 1) * 4;
    int boffw = (wn + (lt >> 1) * 8 + lrow) * SAS + (lt & 1) * 4;

#define ISSUE_E(st, k0)                                                        \
    {                                                                          \
        unsigned dA = dstA0 + (st) * (A_STG * 4);                              \
        const float* sA = srcAbase + (k0);                                     \
        asm volatile("cp.async.cg.shared.global [%0], [%1], 16, %2;"           \
                     :: "r"(dA), "l"(sA), "r"(pa));                            \
        asm volatile("cp.async.cg.shared.global [%0], [%1], 16, %2;"           \
                     :: "r"(dA + 32), "l"(sA + 8), "r"(pa));                   \
        unsigned dB = dstB0 + (st) * (B_STG * 4);                              \
        const float* sB = srcBbase + (k0);                                     \
        asm volatile("cp.async.cg.shared.global [%0], [%1], 16, %2;"           \
                     :: "r"(dB), "l"(sB), "r"(pb));                            \
    }

    int iters = K >> 4;
    ISSUE_E(0, 0);
    asm volatile("cp.async.commit_group;");
    ISSUE_E(1, 16);
    asm volatile("cp.async.commit_group;");
    int stage = 0;
    for (int i = 0; i < iters; i++) {
        asm volatile("cp.async.wait_group 1;");
        __syncthreads();
        int nx = i + 2;
        if (nx < iters) { int nst = nx % STG; ISSUE_E(nst, nx * 16); }
        asm volatile("cp.async.commit_group;");
        unsigned aB = sa_A + (unsigned)(stage * (A_STG * 4) + aoffw * 4);
        unsigned bB = sa_B + (unsigned)(stage * (B_STG * 4) + boffw * 4);
#pragma unroll
        for (int ks = 0; ks < 2; ks++) {
            unsigned kbb = ks * 32;
            unsigned a[2][4];
            ldsm4(a[0][0], a[0][1], a[0][2], a[0][3], aB + kbb);
            ldsm4(a[1][0], a[1][1], a[1][2], a[1][3], aB + kbb + 16 * SAS * 4);
            unsigned b[4][2];
            ldsm4(b[0][0], b[0][1], b[1][0], b[1][1], bB + kbb);
            ldsm4(b[2][0], b[2][1], b[3][0], b[3][1], bB + kbb + 16 * SAS * 4);
#pragma unroll
            for (int im = 0; im < 2; im++)
#pragma unroll
                for (int q = 0; q < 4; q++) a[im][q] = u2tf(a[im][q]);
#pragma unroll
            for (int in = 0; in < 4; in++) {
                b[in][0] = u2tf(b[in][0]);
                b[in][1] = u2tf(b[in][1]);
            }
#pragma unroll
            for (int im = 0; im < 2; im++)
#pragma unroll
                for (int in = 0; in < 4; in++) MMA_TF32(acc[im][in], a[im], b[in]);
        }
        stage = (stage + 1 == STG) ? 0 : stage + 1;
    }
#undef ISSUE_E

    // epilogue + fused BN statistics
    float scol[8], qcol[8];
#pragma unroll
    for (int k2 = 0; k2 < 8; k2++) { scol[k2] = 0.f; qcol[k2] = 0.f; }

#pragma unroll
    for (int im = 0; im < 2; im++) {
#pragma unroll
        for (int in = 0; in < 4; in++) {
            int Cc = wn + in * 8 + 2 * tig;
            float bx = bias[Cc], by = bias[Cc + 1];
            int R0 = row0 + wm + im * 16 + g;
            float v0 = fmaxf(acc[im][in][0] + bx, 0.f);
            float v1 = fmaxf(acc[im][in][1] + by, 0.f);
            float v2 = fmaxf(acc[im][in][2] + bx, 0.f);
            float v3 = fmaxf(acc[im][in][3] + by, 0.f);
            if (R0 < M)
                *reinterpret_cast<float2*>(C + (size_t)R0 * ldc + Cc) = make_float2(v0, v1);
            if (R0 + 8 < M)
                *reinterpret_cast<float2*>(C + (size_t)(R0 + 8) * ldc + Cc) = make_float2(v2, v3);
            float m0 = (R0 < M) ? 1.f : 0.f;
            float m1 = (R0 + 8 < M) ? 1.f : 0.f;
            scol[in * 2 + 0] += m0 * v0 + m1 * v2;
            scol[in * 2 + 1] += m0 * v1 + m1 * v3;
            qcol[in * 2 + 0] += m0 * v0 * v0 + m1 * v2 * v2;
            qcol[in * 2 + 1] += m0 * v1 * v1 + m1 * v3 * v3;
        }
    }
#pragma unroll
    for (int k2 = 0; k2 < 8; k2++) {
#pragma unroll
        for (int mask = 4; mask < 32; mask <<= 1) {
            scol[k2] += __shfl_xor_sync(0xffffffffu, scol[k2], mask);
            qcol[k2] += __shfl_xor_sync(0xffffffffu, qcol[k2], mask);
        }
    }
    if (g == 0) {
#pragma unroll
        for (int k2 = 0; k2 < 8; k2++) {
            int col = wn + (k2 >> 1) * 8 + 2 * tig + (k2 & 1);
            atomicAdd(&g_sum[col], scol[k2]);
            atomicAdd(&g_sumsq[col], qcol[k2]);
        }
    }
}

// ---------------------------------------------------------------------------
// Fused MLP on fp16 mma.m16n8k16: out = relu(z16 @ W1^T + b1) @ W2^T + b2.
// ---------------------------------------------------------------------------
#define A2_STG (128 * 12)
#define B2_STG (64 * 12)

__global__ void k_mlp(const float* __restrict__ b1, const float* __restrict__ b2,
                      float* __restrict__ out) {
    extern __shared__ unsigned dsm[];
    unsigned* As  = dsm;
    unsigned* Bs  = dsm + STG * A2_STG;
    unsigned* hid = dsm;                // reused after sync
    unsigned* W2s = dsm + 128 * 36;

    int t = threadIdx.x;
    int w = t >> 5, lane = t & 31;
    int g = lane >> 2, tig = lane & 3;
    int wm = (w & 3) * 32;
    int wn = (w >> 2) * 32;
    int row0 = blockIdx.x * 128;

    float acc[2][4][4];
#pragma unroll
    for (int im = 0; im < 2; im++)
#pragma unroll
        for (int in = 0; in < 4; in++)
#pragma unroll
            for (int q = 0; q < 4; q++) acc[im][in][q] = 0.f;

    int ar = t >> 1, ac = t & 1;     // A: 2 threads/row, 16B each (32B rows)
    int gr = row0 + ar;
    int pa = (gr < NN) ? 16 : 0;
    const char* srcAbase = (const char*)g_z16 + (size_t)(gr < NN ? gr : NN - 1) * 640 + ac * 16;
    int doB = (t < 128);             // only first 128 threads own B staging
    int br = (t & 127) >> 1, bc = t & 1;
    const char* srcBbase = (const char*)g_W116 + br * 640 + bc * 16;

    unsigned sa_A = (unsigned)__cvta_generic_to_shared(&As[0]);
    unsigned sa_B = (unsigned)__cvta_generic_to_shared(&Bs[0]);
    unsigned dstA0 = sa_A + (unsigned)(ar * 12 + ac * 4) * 4;
    unsigned dstB0 = sa_B + (unsigned)(br * 12 + bc * 4) * 4;

    int lrow = lane & 7, lt = lane >> 3;
    int aoffw = (wm + (lt & 1) * 8 + lrow) * 12 + (lt >> 1) * 4;
    int boffw = (wn + (lt >> 1) * 8 + lrow) * 12 + (lt & 1) * 4;

#define ISSUE_M(st, kb)                                                        \
    {                                                                          \
        unsigned dA = dstA0 + (st) * (A2_STG * 4);                             \
        asm volatile("cp.async.cg.shared.global [%0], [%1], 16, %2;"           \
                     :: "r"(dA), "l"(srcAbase + (kb)), "r"(pa));               \
        if (doB) {                                                             \
            unsigned dB = dstB0 + (st) * (B2_STG * 4);                         \
            asm volatile("cp.async.cg.shared.global [%0], [%1], 16;"           \
                         :: "r"(dB), "l"(srcBbase + (kb)));                    \
        }                                                                      \
    }

    const int iters = ZF / 16;  // 20
    ISSUE_M(0, 0);
    asm volatile("cp.async.commit_group;");
    ISSUE_M(1, 32);
    asm volatile("cp.async.commit_group;");
    int stage = 0;
    for (int i = 0; i < iters; i++) {
        asm volatile("cp.async.wait_group 1;");
        __syncthreads();
        int nx = i + 2;
        if (nx < iters) { int nst = nx % STG; ISSUE_M(nst, nx * 32); }
        asm volatile("cp.async.commit_group;");

        unsigned aB = sa_A + (unsigned)(stage * (A2_STG * 4) + aoffw * 4);
        unsigned bB = sa_B + (unsigned)(stage * (B2_STG * 4) + boffw * 4);
        unsigned a[2][4], b[4][2];
        ldsm4(a[0][0], a[0][1], a[0][2], a[0][3], aB);
        ldsm4(a[1][0], a[1][1], a[1][2], a[1][3], aB + 16 * 12 * 4);
        ldsm4(b[0][0], b[0][1], b[1][0], b[1][1], bB);
        ldsm4(b[2][0], b[2][1], b[3][0], b[3][1], bB + 16 * 12 * 4);
#pragma unroll
        for (int im = 0; im < 2; im++)
#pragma unroll
            for (int in = 0; in < 4; in++) MMA_F16(acc[im][in], a[im], b[in]);

        stage = (stage + 1 == STG) ? 0 : stage + 1;
    }
#undef ISSUE_M

    __syncthreads();  // done with As/Bs; reuse as hid

    // stage-1 epilogue -> smem hid (fp16)
#pragma unroll
    for (int im = 0; im < 2; im++) {
#pragma unroll
        for (int in = 0; in < 4; in++) {
            int Cc = wn + in * 8 + 2 * tig;
            float bx = b1[Cc], by = b1[Cc + 1];
            int rl = wm + im * 16 + g;
            __half2 h0 = __floats2half2_rn(fmaxf(acc[im][in][0] + bx, 0.f),
                                           fmaxf(acc[im][in][1] + by, 0.f));
            __half2 h1 = __floats2half2_rn(fmaxf(acc[im][in][2] + bx, 0.f),
                                           fmaxf(acc[im][in][3] + by, 0.f));
            hid[rl * 36 + (Cc >> 1)]       = *reinterpret_cast<unsigned*>(&h0);
            hid[(rl + 8) * 36 + (Cc >> 1)] = *reinterpret_cast<unsigned*>(&h1);
        }
    }
    // W2 fp16 into smem (64 rows x 32 words)
    for (int id = t; id < 64 * 32; id += 256) {
        int r = id >> 5, c = id & 31;
        W2s[r * 36 + c] = g_W216[id];
    }
    __syncthreads();

    // stage 2: out_tile = hid(128x64) @ W2^T, 4 k16-iters
    float acc2[2][4][4];
#pragma unroll
    for (int im = 0; im < 2; im++)
#pragma unroll
        for (int in = 0; in < 4; in++)
#pragma unroll
            for (int q = 0; q < 4; q++) acc2[im][in][q] = 0.f;

    unsigned sa_h  = (unsigned)__cvta_generic_to_shared(hid);
    unsigned sa_w2 = (unsigned)__cvta_generic_to_shared(W2s);
    unsigned a2off = sa_h  + (unsigned)((wm + (lt & 1) * 8 + lrow) * 36 + (lt >> 1) * 4) * 4;
    unsigned b2off = sa_w2 + (unsigned)((wn + (lt >> 1) * 8 + lrow) * 36 + (lt & 1) * 4) * 4;

#pragma unroll
    for (int ks = 0; ks < 4; ks++) {
        unsigned kbb = ks * 32;
        unsigned a[2][4], b[4][2];
        ldsm4(a[0][0], a[0][1], a[0][2], a[0][3], a2off + kbb);
        ldsm4(a[1][0], a[1][1], a[1][2], a[1][3], a2off + kbb + 16 * 36 * 4);
        ldsm4(b[0][0], b[0][1], b[1][0], b[1][1], b2off + kbb);
        ldsm4(b[2][0], b[2][1], b[3][0], b[3][1], b2off + kbb + 16 * 36 * 4);
#pragma unroll
        for (int im = 0; im < 2; im++)
#pragma unroll
            for (int in = 0; in < 4; in++) MMA_F16(acc2[im][in], a[im], b[in]);
    }

    // stage-2 epilogue -> out [NN x CF]
#pragma unroll
    for (int im = 0; im < 2; im++) {
#pragma unroll
        for (int in = 0; in < 4; in++) {
            int Cc = wn + in * 8 + 2 * tig;
            if (Cc >= CF) continue;
            float bx = b2[Cc], by = b2[Cc + 1];
            int R0 = row0 + wm + im * 16 + g;
            if (R0 < NN)
                *reinterpret_cast<float2*>(out + (size_t)R0 * CF + Cc) =
                    make_float2(acc2[im][in][0] + bx, acc2[im][in][1] + by);
            if (R0 + 8 < NN)
                *reinterpret_cast<float2*>(out + (size_t)(R0 + 8) * CF + Cc) =
                    make_float2(acc2[im][in][2] + bx, acc2[im][in][3] + by);
        }
    }
}

// ---------------------------------------------------------------------------
// BN finalize + apply: reads fp32 h, writes fp16 z chunk0 + premult shadow.
// ---------------------------------------------------------------------------
__global__ void k_bnapply(const float* __restrict__ gamma, const float* __restrict__ beta) {
    int i = blockIdx.x * blockDim.x + threadIdx.x;
    if (i >= NN * 32) return;
    int node = i >> 5, fp = (i & 31) * 2;
    float2 sc, sh;
#pragma unroll
    for (int q = 0; q < 2; q++) {
        int f = fp + q;
        float mu = g_sum[f] * (1.f / (float)NN);
        float var = g_sumsq[f] * (1.f / (float)NN) - mu * mu;
        float s = gamma[f] * rsqrtf(var + 1e-5f);
        float b = beta[f] - mu * s;
        if (q == 0) { sc.x = s; sh.x = b; } else { sc.y = s; sh.y = b; }
    }
    float2 v = *reinterpret_cast<const float2*>(g_z + (size_t)node * HF + fp);
    v.x = v.x * sc.x + sh.x;
    v.y = v.y * sc.y + sh.y;
    __half2 hz = __floats2half2_rn(v.x, v.y);
    g_z16[(size_t)node * ZW + (i & 31)] = *reinterpret_cast<unsigned*>(&hz);
    float dn = g_dinv[node];
    __half2 hv = __floats2half2_rn(v.x * dn, v.y * dn);
    g_h16[(size_t)node * 32 + (i & 31)] = *reinterpret_cast<unsigned*>(&hv);
}

// ---------------------------------------------------------------------------
// SpMM (R14 shape): HALF-WARP per node, 16 lanes x fp16x4 gathers of the
// premultiplied shadow chunk srcC. dst = du * sum (- wsq*prev). Writes raw
// fp16 z chunk (dstW words); premult shadow if dstC>=0; cur if writeCur.
// prevMode: 0 none, 1 z16 chunk0 (h), 2 g_cur16.
// ---------------------------------------------------------------------------
__global__ void k_spmm(int srcC, int prevMode, int dstW, int dstC, int writeCur) {
    int node = blockIdx.x * 16 + (threadIdx.x >> 4);
    if (node >= NN) return;
    int lane = threadIdx.x & 15;

    const unsigned* src16 = g_h16 + (size_t)srcC * NN * 32;

    int s = g_rowptr[node];
    int e = g_rowptr[node + 1];
    float ax = 0.f, ay = 0.f, az = 0.f, aw = 0.f;
#pragma unroll 4
    for (int j = s; j < e; j++) {
        int v = g_adj[j];
        uint2 wv = __ldg(reinterpret_cast<const uint2*>(src16 + (size_t)v * 32 + lane * 2));
        float2 p0 = __half22float2(*reinterpret_cast<__half2*>(&wv.x));
        float2 p1 = __half22float2(*reinterpret_cast<__half2*>(&wv.y));
        ax += p0.x;
        ay += p0.y;
        az += p1.x;
        aw += p1.y;
    }
    float du = g_dinv[node];
    ax *= du; ay *= du; az *= du; aw *= du;
    if (prevMode) {
        const unsigned* pv = (prevMode == 1) ? (g_z16 + (size_t)node * ZW)
                                             : (g_cur16 + (size_t)node * 32);
        float wsq = g_wsq[node];
        uint2 pw = *reinterpret_cast<const uint2*>(pv + lane * 2);
        float2 q0 = __half22float2(*reinterpret_cast<__half2*>(&pw.x));
        float2 q1 = __half22float2(*reinterpret_cast<__half2*>(&pw.y));
        ax -= wsq * q0.x;
        ay -= wsq * q0.y;
        az -= wsq * q1.x;
        aw -= wsq * q1.y;
    }
    {
        __half2 h0 = __floats2half2_rn(ax, ay);
        __half2 h1 = __floats2half2_rn(az, aw);
        uint2 st = make_uint2(*reinterpret_cast<unsigned*>(&h0),
                              *reinterpret_cast<unsigned*>(&h1));
        *reinterpret_cast<uint2*>(g_z16 + (size_t)node * ZW + dstW + lane * 2) = st;
    }
    if (dstC >= 0) {
        __half2 h0 = __floats2half2_rn(ax * du, ay * du);
        __half2 h1 = __floats2half2_rn(az * du, aw * du);
        uint2 st = make_uint2(*reinterpret_cast<unsigned*>(&h0),
                              *reinterpret_cast<unsigned*>(&h1));
        *reinterpret_cast<uint2*>(g_h16 + (size_t)dstC * NN * 32 +
                                  (size_t)node * 32 + lane * 2) = st;
    }
    if (writeCur) {
        uint2 rw = *reinterpret_cast<const uint2*>(g_z16 + (size_t)node * ZW + 32 + lane * 2);
        float2 r0 = __half22float2(*reinterpret_cast<__half2*>(&rw.x));
        float2 r1 = __half22float2(*reinterpret_cast<__half2*>(&rw.y));
        float cx = r0.x + ax, cy = r0.y + ay, cz = r1.x + az, cw = r1.y + aw;
        __half2 c0 = __floats2half2_rn(cx, cy);
        __half2 c1 = __floats2half2_rn(cz, cw);
        uint2 st = make_uint2(*reinterpret_cast<unsigned*>(&c0),
                              *reinterpret_cast<unsigned*>(&c1));
        *reinterpret_cast<uint2*>(g_cur16 + (size_t)node * 32 + lane * 2) = st;
        __half2 s0 = __floats2half2_rn(cx * du, cy * du);
        __half2 s1 = __floats2half2_rn(cz * du, cw * du);
        uint2 sp = make_uint2(*reinterpret_cast<unsigned*>(&s0),
                              *reinterpret_cast<unsigned*>(&s1));
        *reinterpret_cast<uint2*>(g_h16 + (size_t)2 * NN * 32 +
                                  (size_t)node * 32 + lane * 2) = sp;
    }
}

// ---------------------------------------------------------------------------
extern "C" void kernel_launch(void* const* d_in, const int* in_sizes, int n_in,
                              void* d_out, int out_size) {
    const float* x       = (const float*)d_in[0];
    const int*   ei32    = (const int*)d_in[1];
    const float* W_embed = (const float*)d_in[2];
    const float* b_embed = (const float*)d_in[3];
    const float* bn_g    = (const float*)d_in[4];
    const float* bn_b    = (const float*)d_in[5];
    const float* W1      = (const float*)d_in[6];
    const float* b1      = (const float*)d_in[7];
    const float* W2      = (const float*)d_in[8];
    const float* b2      = (const float*)d_in[9];
    float* out = (float*)d_out;

    const int NPART = (NN + 255) / 256;
    int mma_grid = (NN + 127) / 128;
    int warp8_grid = (NN + 7) / 8;

    // zero BN accumulators, then fork embed GEMM onto s2 (overlaps graph prep)
    k_zero<<<1, 128>>>();
    if (g_fork) {
        cudaEventRecord(g_e1, 0);
        cudaStreamWaitEvent(g_s2, g_e1, 0);
        k_mma<<<mma_grid, 256, 0, g_s2>>>(x, NN, INF_, INF_, W_embed, HF, INF_, b_embed);
        cudaEventRecord(g_e2, g_s2);
    } else {
        k_mma<<<mma_grid, 256>>>(x, NN, INF_, INF_, W_embed, HF, INF_, b_embed);
    }

    // graph prep on main stream (independent of embed)
    k_init<<<256, 256>>>(ei32);
    k_cvtW<<<40, 256>>>(W1, W2);
    k_deg<<<(EE + 255) / 256, 256>>>(ei32);
    k_scan1<<<NPART, 256>>>();
    k_scan2<<<1, 512>>>(NPART);
    k_scan3<<<NPART, 256>>>();
    k_fill<<<(EE + 255) / 256, 256>>>(ei32);
    k_wsq<<<warp8_grid, 256>>>();

    // join: BN apply needs embed output + stats (+ dinv for the shadow)
    if (g_fork) cudaStreamWaitEvent(0, g_e2, 0);
    k_bnapply<<<(NN * 32 + 255) / 256, 256>>>(bn_g, bn_b);

    int spmm_grid = (NN + 15) / 16;
    // hop 1: h1a = A h ; h2a = A h1a - diag2*h ; cur = h1a + h2a
    k_spmm<<<spmm_grid, 256>>>(0, 0, 32, 1, 0);
    k_spmm<<<spmm_grid, 256>>>(1, 1, 64, -1, 1);
    // hop 2: h1b = A cur ; h2b = A h1b - diag2*cur
    k_spmm<<<spmm_grid, 256>>>(2, 0, 96, 3, 0);
    k_spmm<<<spmm_grid, 256>>>(3, 2, 128, -1, 0);

    // fused fp16 MLP
    cudaFuncSetAttribute(k_mlp, cudaFuncAttributeMaxDynamicSharedMemorySize, 27648);
    k_mlp<<<mma_grid, 256, 27648>>>(b1, b2, out);
}